// round 5
// baseline (speedup 1.0000x reference)
#include <cuda_runtime.h>
#include <cstdint>
#include <cstddef>

// Problem constants (fixed by the reference)
#define BB 256
#define CC 32
#define HH 64
#define WW 64
#define PW 68           // padded width/height (2-px zero ring for 5x5 SAME)
#define PIMG (PW*PW)    // 4624

// ---------------------------------------------------------------------------
// Device-global scratch (allocation-free rule: __device__ globals only).
// Zero-initialized at module load; padding rings are also re-zeroed every
// launch by zero_borders so repeated graph replays stay deterministic.
// ---------------------------------------------------------------------------
__device__ float g_h [(size_t)BB * CC * PIMG];   // rotated input, padded
__device__ float g_y1[(size_t)BB * 64 * PIMG];   // conv1 output, padded
__device__ float g_y2[(size_t)BB * 64 * PIMG];   // conv2 output, padded

// ---------------------------------------------------------------------------
// Packed dual-fp32 helpers (Blackwell f32x2 path: 2x FFMA throughput)
// ---------------------------------------------------------------------------
__device__ __forceinline__ void fma2(unsigned long long& d,
                                     unsigned long long a,
                                     unsigned long long b) {
    asm("fma.rn.f32x2 %0, %1, %2, %0;" : "+l"(d) : "l"(a), "l"(b));
}

__device__ __forceinline__ unsigned long long packf2(float lo, float hi) {
    unsigned long long r;
    asm("mov.b64 %0, {%1, %2};" : "=l"(r) : "f"(lo), "f"(hi));
    return r;
}

// ---------------------------------------------------------------------------
// Kernel 1: rotation. One block per (b, c). The source image for channel c is
// the row x[b,0,c,:] replicated over all 64 rows, so the bilinear sample is
// separable:  val = fy(valid-y weights) * (wx0*row[x0] + wx1*row[x1]).
// Writes the full padded 68x68 (ring = 0).
// ---------------------------------------------------------------------------
__global__ void rotate_kernel(const float* __restrict__ xin,
                              float* __restrict__ hout)
{
    const int bc = blockIdx.x;          // b*32 + c
    const int c  = bc & (CC - 1);

    __shared__ float row[WW];
    if (threadIdx.x < WW) row[threadIdx.x] = xin[(size_t)bc * WW + threadIdx.x];
    __syncthreads();

    // Match reference fp32 semantics: deg2rad(-180/32 * c) in fp32.
    const float ang = (-180.0f / 32.0f) * (float)c * 0.017453292519943295f;
    float si, co;
    sincosf(ang, &si, &co);

    float* dst = hout + (size_t)bc * PIMG;
    for (int p = threadIdx.x; p < PIMG; p += blockDim.x) {
        const int py = p / PW;
        const int px = p - py * PW;
        const int y = py - 2, x = px - 2;
        float val = 0.f;
        if ((unsigned)y < 64u && (unsigned)x < 64u) {
            const float xx = (float)x - 31.5f;
            const float yy = (float)y - 31.5f;
            const float xs = co * xx + si * yy + 31.5f;
            const float ys = co * yy - si * xx + 31.5f;
            const float x0f = floorf(xs);
            const float y0f = floorf(ys);
            const int x0  = (int)x0f;
            const int y0i = (int)y0f;
            const float wx1 = xs - x0f, wx0 = 1.f - wx1;
            const float wy1 = ys - y0f, wy0 = 1.f - wy1;
            float fy = 0.f;
            if ((unsigned)y0i       < 64u) fy += wy0;
            if ((unsigned)(y0i + 1) < 64u) fy += wy1;
            float fx = 0.f;
            if ((unsigned)x0       < 64u) fx += wx0 * row[x0];
            if ((unsigned)(x0 + 1) < 64u) fx += wx1 * row[x0 + 1];
            val = fy * fx;
        }
        dst[p] = val;
    }
}

// ---------------------------------------------------------------------------
// Re-zero the padding ring of both conv scratch buffers (the conv kernels
// never write the ring; zero ring == SAME zero padding). 528 elems per (b,ch).
// ---------------------------------------------------------------------------
__global__ void zero_borders(float* __restrict__ a, float* __restrict__ b)
{
    const int bc = blockIdx.x;          // b*64 + ch, 16384 blocks
    float* pa = a + (size_t)bc * PIMG;
    float* pb = b + (size_t)bc * PIMG;
    for (int p = threadIdx.x; p < 528; p += blockDim.x) {
        int off;
        if (p < 136)        off = p;                         // rows 0,1
        else if (p < 272)   off = 66 * PW + (p - 136);       // rows 66,67
        else {
            const int q = p - 272;                           // 256 entries
            const int r = 2 + (q >> 2);                      // rows 2..65
            const int cc4 = q & 3;
            const int col = (cc4 < 2) ? cc4 : 64 + cc4;      // cols 0,1,66,67
            off = r * PW + col;
        }
        pa[off] = 0.f;
        pb[off] = 0.f;
    }
}

// ---------------------------------------------------------------------------
// Kernel 2/3: 5x5 SAME conv, CIN -> 64, ReLU, padded in / padded out.
// Block = (image b, 4-row tile). 256 threads = 8 warps.
//   warp w -> output channels [8w, 8w+8)
//   lane l -> output columns {2l, 2l+1} packed into one f32x2 accumulator
// smem: input slab CIN x 8rows x 68cols + per-c weight slice duplicated to
// (w,w) float2 so the inner loop is LDS.64 + fma.rn.f32x2 only.
// ---------------------------------------------------------------------------
template <int CIN>
__global__ void __launch_bounds__(256, 1)
conv5x5_relu(const float* __restrict__ in,    // [B][CIN][68][68]
             const float* __restrict__ w,     // [64][CIN][5][5]
             const float* __restrict__ bias,  // [64]
             float* __restrict__ out)         // [B][64][68][68]
{
    extern __shared__ float smem[];
    float*  tile = smem;                              // CIN*8*68 floats
    float2* wp   = (float2*)(smem + CIN * 8 * PW);    // 64*25 float2

    const int blk   = blockIdx.x;
    const int ytile = blk & 15;
    const int b     = blk >> 4;
    const int y0    = ytile * 4;

    // Load input slab: padded rows y0..y0+7, all 68 cols, all CIN channels.
    const float* src = in + (size_t)b * CIN * PIMG + (size_t)y0 * PW;
    const int tsz = CIN * 8 * PW;
    for (int i = threadIdx.x; i < tsz; i += 256) {
        const int ch = i / (8 * PW);
        const int r  = i - ch * (8 * PW);
        tile[i] = src[(size_t)ch * PIMG + r];
    }

    const int warp   = threadIdx.x >> 5;
    const int lane   = threadIdx.x & 31;
    const int ocbase = warp * 8;

    unsigned long long acc[8][4];
#pragma unroll
    for (int j = 0; j < 8; ++j)
#pragma unroll
        for (int yr = 0; yr < 4; ++yr) acc[j][yr] = 0ull;

#pragma unroll 1
    for (int c = 0; c < CIN; ++c) {
        __syncthreads();   // protects tile (iter 0) and previous wp readers
        // Stage w[:, c, :, :] duplicated into float2 pairs.
        for (int i = threadIdx.x; i < 64 * 25; i += 256) {
            const int oc = i / 25;
            const int k  = i - oc * 25;
            const float wv = w[((size_t)oc * CIN + c) * 25 + k];
            wp[i] = make_float2(wv, wv);
        }
        __syncthreads();

        const float* trow = tile + c * (8 * PW) + 2 * lane;
#pragma unroll
        for (int ky = 0; ky < 5; ++ky) {
            // Build the 5 shifted column pairs for each of the 4 output rows.
            unsigned long long p0[4], p1[4], p2[4], p3[4], p4[4];
#pragma unroll
            for (int yr = 0; yr < 4; ++yr) {
                const float2* t2 = (const float2*)(trow + (ky + yr) * PW);
                const float2 v01 = t2[0];
                const float2 v23 = t2[1];
                const float2 v45 = t2[2];
                p0[yr] = packf2(v01.x, v01.y);
                p1[yr] = packf2(v01.y, v23.x);
                p2[yr] = packf2(v23.x, v23.y);
                p3[yr] = packf2(v23.y, v45.x);
                p4[yr] = packf2(v45.x, v45.y);
            }
            const unsigned long long* wrow =
                (const unsigned long long*)wp + ky * 5;
#pragma unroll
            for (int j = 0; j < 8; ++j) {
                const unsigned long long* wj = wrow + (size_t)(ocbase + j) * 25;
                const unsigned long long w0v = wj[0];
                const unsigned long long w1v = wj[1];
                const unsigned long long w2v = wj[2];
                const unsigned long long w3v = wj[3];
                const unsigned long long w4v = wj[4];
#pragma unroll
                for (int yr = 0; yr < 4; ++yr) {
                    fma2(acc[j][yr], w0v, p0[yr]);
                    fma2(acc[j][yr], w1v, p1[yr]);
                    fma2(acc[j][yr], w2v, p2[yr]);
                    fma2(acc[j][yr], w3v, p3[yr]);
                    fma2(acc[j][yr], w4v, p4[yr]);
                }
            }
        }
    }

    // Epilogue: bias + ReLU, write padded interior (rows y0+2.., cols 2..65).
    const size_t ob = (size_t)b * 64;
#pragma unroll
    for (int j = 0; j < 8; ++j) {
        const int oc = ocbase + j;
        const float bv = bias[oc];
#pragma unroll
        for (int yr = 0; yr < 4; ++yr) {
            const float lo = __uint_as_float((unsigned)(acc[j][yr] & 0xffffffffull));
            const float hi = __uint_as_float((unsigned)(acc[j][yr] >> 32));
            float2 o;
            o.x = fmaxf(lo + bv, 0.f);
            o.y = fmaxf(hi + bv, 0.f);
            *(float2*)(out + (ob + oc) * PIMG
                           + (size_t)(y0 + 2 + yr) * PW + 2 + 2 * lane) = o;
        }
    }
}

// ---------------------------------------------------------------------------
// Kernel 4: final 5x5 conv, 64 -> 1, no ReLU, writes d_out (B,64,64).
// Block = (b, 4-row tile), one output pixel per thread. Only 1.7 GMAC total.
// ---------------------------------------------------------------------------
__global__ void __launch_bounds__(256, 1)
conv3k(const float* __restrict__ in,   // [B][64][68][68]
       const float* __restrict__ w2,   // [1][64][5][5]
       const float* __restrict__ b2,   // [1]
       float* __restrict__ out)        // [B][64][64]
{
    extern __shared__ float smem[];
    float* tile = smem;                 // 64*8*68
    float* ws   = smem + 64 * 8 * PW;   // 1600

    const int blk   = blockIdx.x;
    const int ytile = blk & 15;
    const int b     = blk >> 4;
    const int y0    = ytile * 4;

    const float* src = in + (size_t)b * 64 * PIMG + (size_t)y0 * PW;
    for (int i = threadIdx.x; i < 64 * 8 * PW; i += 256) {
        const int ch = i / (8 * PW);
        const int r  = i - ch * (8 * PW);
        tile[i] = src[(size_t)ch * PIMG + r];
    }
    for (int i = threadIdx.x; i < 1600; i += 256) ws[i] = w2[i];
    __syncthreads();

    const int yr = threadIdx.x >> 6;    // 0..3
    const int x  = threadIdx.x & 63;    // 0..63
    float acc = b2[0];
#pragma unroll 1
    for (int c = 0; c < 64; ++c) {
        const float* t  = tile + c * (8 * PW) + yr * PW + x;
        const float* wc = ws + c * 25;
#pragma unroll
        for (int ky = 0; ky < 5; ++ky)
#pragma unroll
            for (int kx = 0; kx < 5; ++kx)
                acc += wc[ky * 5 + kx] * t[ky * PW + kx];
    }
    out[(size_t)b * 4096 + (size_t)(y0 + yr) * 64 + x] = acc;
}

// ---------------------------------------------------------------------------
// kernel_launch: graph-capturable (kernel launches only; symbol-address and
// func-attribute queries are non-stream APIs, legal under capture).
// Input order per metadata: x, w0, b0, w1, b1, w2, b2 (all fp32).
// ---------------------------------------------------------------------------
extern "C" void kernel_launch(void* const* d_in, const int* in_sizes, int n_in,
                              void* d_out, int out_size)
{
    (void)in_sizes; (void)n_in; (void)out_size;

    const float* x  = (const float*)d_in[0];
    const float* w0 = (const float*)d_in[1];
    const float* b0 = (const float*)d_in[2];
    const float* w1 = (const float*)d_in[3];
    const float* b1 = (const float*)d_in[4];
    const float* w2 = (const float*)d_in[5];
    const float* b2 = (const float*)d_in[6];
    float* out = (float*)d_out;

    void *ph, *py1, *py2;
    cudaGetSymbolAddress(&ph,  g_h);
    cudaGetSymbolAddress(&py1, g_y1);
    cudaGetSymbolAddress(&py2, g_y2);

    constexpr int SMEM1 = (32 * 8 * PW + 64 * 25 * 2) * 4;  //  82,432 B
    constexpr int SMEM2 = (64 * 8 * PW + 64 * 25 * 2) * 4;  // 152,064 B
    constexpr int SMEM3 = (64 * 8 * PW + 1600) * 4;         // 145,664 B

    cudaFuncSetAttribute(conv5x5_relu<32>,
                         cudaFuncAttributeMaxDynamicSharedMemorySize, SMEM1);
    cudaFuncSetAttribute(conv5x5_relu<64>,
                         cudaFuncAttributeMaxDynamicSharedMemorySize, SMEM2);
    cudaFuncSetAttribute(conv3k,
                         cudaFuncAttributeMaxDynamicSharedMemorySize, SMEM3);

    rotate_kernel<<<BB * CC, 128>>>(x, (float*)ph);
    zero_borders<<<BB * 64, 128>>>((float*)py1, (float*)py2);
    conv5x5_relu<32><<<BB * 16, 256, SMEM1>>>((const float*)ph, w0, b0, (float*)py1);
    conv5x5_relu<64><<<BB * 16, 256, SMEM2>>>((const float*)py1, w1, b1, (float*)py2);
    conv3k<<<BB * 16, 256, SMEM3>>>((const float*)py2, w2, b2, out);
}

// round 6
// speedup vs baseline: 1.3759x; 1.3759x over previous
#include <cuda_runtime.h>
#include <cstdint>
#include <cstddef>

// Problem constants (fixed by the reference)
#define BB 256
#define CC 32
#define HH 64
#define WW 64
#define PW 68           // padded width/height (2-px zero ring for 5x5 SAME)
#define PIMG (PW*PW)    // 4624

#define CHUNK 32        // input channels per tile pass
#define TROWS 8         // padded rows per tile (4 output rows + 4 halo)
#define TSZ   (CHUNK*TROWS*PW)   // floats per tile copy = 17408

// ---------------------------------------------------------------------------
// Device-global scratch (allocation-free rule: __device__ globals only).
// ---------------------------------------------------------------------------
__device__ float g_h [(size_t)BB * CC * PIMG];   // rotated input, padded
__device__ float g_y1[(size_t)BB * 64 * PIMG];   // conv1 output, padded
__device__ float g_y2[(size_t)BB * 64 * PIMG];   // conv2 output, padded

// ---------------------------------------------------------------------------
// Packed dual-fp32 helpers (Blackwell f32x2 path: 2x FFMA throughput)
// ---------------------------------------------------------------------------
__device__ __forceinline__ void fma2(unsigned long long& d,
                                     unsigned long long a,
                                     unsigned long long b) {
    asm("fma.rn.f32x2 %0, %1, %2, %0;" : "+l"(d) : "l"(a), "l"(b));
}

// ---------------------------------------------------------------------------
// Kernel 1: rotation (separable because source rows are replicated).
// ---------------------------------------------------------------------------
__global__ void rotate_kernel(const float* __restrict__ xin,
                              float* __restrict__ hout)
{
    const int bc = blockIdx.x;          // b*32 + c
    const int c  = bc & (CC - 1);

    __shared__ float row[WW];
    if (threadIdx.x < WW) row[threadIdx.x] = xin[(size_t)bc * WW + threadIdx.x];
    __syncthreads();

    const float ang = (-180.0f / 32.0f) * (float)c * 0.017453292519943295f;
    float si, co;
    sincosf(ang, &si, &co);

    float* dst = hout + (size_t)bc * PIMG;
    for (int p = threadIdx.x; p < PIMG; p += blockDim.x) {
        const int py = p / PW;
        const int px = p - py * PW;
        const int y = py - 2, x = px - 2;
        float val = 0.f;
        if ((unsigned)y < 64u && (unsigned)x < 64u) {
            const float xx = (float)x - 31.5f;
            const float yy = (float)y - 31.5f;
            const float xs = co * xx + si * yy + 31.5f;
            const float ys = co * yy - si * xx + 31.5f;
            const float x0f = floorf(xs);
            const float y0f = floorf(ys);
            const int x0  = (int)x0f;
            const int y0i = (int)y0f;
            const float wx1 = xs - x0f, wx0 = 1.f - wx1;
            const float wy1 = ys - y0f, wy0 = 1.f - wy1;
            float fy = 0.f;
            if ((unsigned)y0i       < 64u) fy += wy0;
            if ((unsigned)(y0i + 1) < 64u) fy += wy1;
            float fx = 0.f;
            if ((unsigned)x0       < 64u) fx += wx0 * row[x0];
            if ((unsigned)(x0 + 1) < 64u) fx += wx1 * row[x0 + 1];
            val = fy * fx;
        }
        dst[p] = val;
    }
}

// ---------------------------------------------------------------------------
// Re-zero the padding rings of the conv scratch buffers each launch.
// ---------------------------------------------------------------------------
__global__ void zero_borders(float* __restrict__ a, float* __restrict__ b)
{
    const int bc = blockIdx.x;          // b*64 + ch
    float* pa = a + (size_t)bc * PIMG;
    float* pb = b + (size_t)bc * PIMG;
    for (int p = threadIdx.x; p < 528; p += blockDim.x) {
        int off;
        if (p < 136)        off = p;                         // rows 0,1
        else if (p < 272)   off = 66 * PW + (p - 136);       // rows 66,67
        else {
            const int q = p - 272;
            const int r = 2 + (q >> 2);                      // rows 2..65
            const int cc4 = q & 3;
            const int col = (cc4 < 2) ? cc4 : 64 + cc4;      // cols 0,1,66,67
            off = r * PW + col;
        }
        pa[off] = 0.f;
        pb[off] = 0.f;
    }
}

// ---------------------------------------------------------------------------
// 5x5 SAME conv, CIN -> 64, ReLU. Block = (image, 4-row tile), 256 thr.
//   warp w -> oc [8w,8w+8); lane l -> cols {2l,2l+1} in one f32x2 acc.
// smem: tileA (raw) + tileB (shifted by 1 float -> odd pairs are aligned
//       LDS.64, zero packing MOVs) + per-warp double-buffered dup-weights.
// Weights: per-warp staging with register prefetch of channel c+1 while
// computing channel c; only __syncwarp in the steady-state loop.
// ---------------------------------------------------------------------------
template <int CIN>
__global__ void __launch_bounds__(256, 1)
conv5x5_relu(const float* __restrict__ in,    // [B][CIN][68][68]
             const float* __restrict__ w,     // [64][CIN][5][5]
             const float* __restrict__ bias,  // [64]
             float* __restrict__ out)         // [B][64][68][68]
{
    extern __shared__ float smem[];
    float*  tileA = smem;                      // TSZ floats
    float*  tileB = smem + TSZ;                // TSZ floats (shifted copy)
    float2* wsm   = (float2*)(smem + 2 * TSZ); // 8 warps x 2 bufs x 200 float2

    const int blk   = blockIdx.x;
    const int ytile = blk & 15;
    const int b     = blk >> 4;
    const int y0    = ytile * 4;

    const int warp   = threadIdx.x >> 5;
    const int lane   = threadIdx.x & 31;
    const int ocbase = warp * 8;

    // --- weight prefetch for channel 0 (warp's 8 oc x 25 = 200 floats) ---
    float wreg[7];
#pragma unroll
    for (int it = 0; it < 7; ++it) {
        const int idx = lane + it * 32;
        if (idx < 200) {
            const int jo = idx / 25, k = idx - jo * 25;
            wreg[it] = w[((size_t)(ocbase + jo) * CIN + 0) * 25 + k];
        }
    }

    unsigned long long acc[8][4];
#pragma unroll
    for (int j = 0; j < 8; ++j)
#pragma unroll
        for (int yr = 0; yr < 4; ++yr) acc[j][yr] = 0ull;

    constexpr int NCHUNK = CIN / CHUNK;
#pragma unroll 1
    for (int chunk = 0; chunk < NCHUNK; ++chunk) {
        // ---- load tile for channels [chunk*CHUNK, +CHUNK): raw + shifted ----
        __syncthreads();   // previous chunk fully consumed
        const float* src = in + ((size_t)b * CIN + chunk * CHUNK) * PIMG
                              + (size_t)y0 * PW;
#pragma unroll 1
        for (int i = threadIdx.x; i < TSZ; i += 256) {
            const int ch = i / (TROWS * PW);
            const int r  = i - ch * (TROWS * PW);
            const int x  = r % PW;
            const float v = src[(size_t)ch * PIMG + r];
            tileA[i] = v;
            if (x > 0) tileB[i - 1] = v;
        }
        __syncthreads();

#pragma unroll 1
        for (int cl = 0; cl < CHUNK; ++cl) {
            const int c = chunk * CHUNK + cl;

            // ---- stage prefetched weights (channel c) to smem, dup'd ----
            float2* wb = wsm + (size_t)(warp * 2 + (c & 1)) * 200;
#pragma unroll
            for (int it = 0; it < 7; ++it) {
                const int idx = lane + it * 32;
                if (idx < 200) wb[idx] = make_float2(wreg[it], wreg[it]);
            }
            __syncwarp();

            // ---- prefetch channel c+1 weights into registers ----
            if (c + 1 < CIN) {
#pragma unroll
                for (int it = 0; it < 7; ++it) {
                    const int idx = lane + it * 32;
                    if (idx < 200) {
                        const int jo = idx / 25, k = idx - jo * 25;
                        wreg[it] = w[((size_t)(ocbase + jo) * CIN + (c + 1)) * 25 + k];
                    }
                }
            }

            // ---- compute: all pair operands are aligned LDS.64 ----
            const float* ta = tileA + cl * (TROWS * PW) + 2 * lane;
            const float* tb = tileB + cl * (TROWS * PW) + 2 * lane;
            const unsigned long long* wu = (const unsigned long long*)wb;
#pragma unroll
            for (int ky = 0; ky < 5; ++ky) {
                unsigned long long p0[4], p1[4], p2[4], p3[4], p4[4];
#pragma unroll
                for (int yr = 0; yr < 4; ++yr) {
                    const int ro = (ky + yr) * PW;
                    p0[yr] = *(const unsigned long long*)(ta + ro);
                    p1[yr] = *(const unsigned long long*)(tb + ro);
                    p2[yr] = *(const unsigned long long*)(ta + ro + 2);
                    p3[yr] = *(const unsigned long long*)(tb + ro + 2);
                    p4[yr] = *(const unsigned long long*)(ta + ro + 4);
                }
#pragma unroll
                for (int j = 0; j < 8; ++j) {
                    const unsigned long long* wj = wu + j * 25 + ky * 5;
                    const unsigned long long w0v = wj[0];
                    const unsigned long long w1v = wj[1];
                    const unsigned long long w2v = wj[2];
                    const unsigned long long w3v = wj[3];
                    const unsigned long long w4v = wj[4];
#pragma unroll
                    for (int yr = 0; yr < 4; ++yr) {
                        fma2(acc[j][yr], w0v, p0[yr]);
                        fma2(acc[j][yr], w1v, p1[yr]);
                        fma2(acc[j][yr], w2v, p2[yr]);
                        fma2(acc[j][yr], w3v, p3[yr]);
                        fma2(acc[j][yr], w4v, p4[yr]);
                    }
                }
            }
        }
    }

    // ---- epilogue: bias + ReLU, write padded interior ----
    const size_t ob = (size_t)b * 64;
#pragma unroll
    for (int j = 0; j < 8; ++j) {
        const int oc = ocbase + j;
        const float bv = bias[oc];
#pragma unroll
        for (int yr = 0; yr < 4; ++yr) {
            const float lo = __uint_as_float((unsigned)(acc[j][yr] & 0xffffffffull));
            const float hi = __uint_as_float((unsigned)(acc[j][yr] >> 32));
            float2 o;
            o.x = fmaxf(lo + bv, 0.f);
            o.y = fmaxf(hi + bv, 0.f);
            *(float2*)(out + (ob + oc) * PIMG
                           + (size_t)(y0 + 2 + yr) * PW + 2 + 2 * lane) = o;
        }
    }
}

// ---------------------------------------------------------------------------
// Final 5x5 conv, 64 -> 1, writes d_out (B,64,64). ~1.7 GMAC total.
// ---------------------------------------------------------------------------
__global__ void __launch_bounds__(256, 1)
conv3k(const float* __restrict__ in,   // [B][64][68][68]
       const float* __restrict__ w2,   // [1][64][5][5]
       const float* __restrict__ b2,   // [1]
       float* __restrict__ out)        // [B][64][64]
{
    extern __shared__ float smem[];
    float* tile = smem;                 // 64*8*68
    float* ws   = smem + 64 * 8 * PW;   // 1600

    const int blk   = blockIdx.x;
    const int ytile = blk & 15;
    const int b     = blk >> 4;
    const int y0    = ytile * 4;

    const float* src = in + (size_t)b * 64 * PIMG + (size_t)y0 * PW;
    for (int i = threadIdx.x; i < 64 * 8 * PW; i += 256) {
        const int ch = i / (8 * PW);
        const int r  = i - ch * (8 * PW);
        tile[i] = src[(size_t)ch * PIMG + r];
    }
    for (int i = threadIdx.x; i < 1600; i += 256) ws[i] = w2[i];
    __syncthreads();

    const int yr = threadIdx.x >> 6;    // 0..3
    const int x  = threadIdx.x & 63;    // 0..63
    float acc = b2[0];
#pragma unroll 1
    for (int c = 0; c < 64; ++c) {
        const float* t  = tile + c * (8 * PW) + yr * PW + x;
        const float* wc = ws + c * 25;
#pragma unroll
        for (int ky = 0; ky < 5; ++ky)
#pragma unroll
            for (int kx = 0; kx < 5; ++kx)
                acc += wc[ky * 5 + kx] * t[ky * PW + kx];
    }
    out[(size_t)b * 4096 + (size_t)(y0 + yr) * 64 + x] = acc;
}

// ---------------------------------------------------------------------------
// kernel_launch (graph-capturable: kernel launches + non-stream queries only)
// Input order per metadata: x, w0, b0, w1, b1, w2, b2 (all fp32).
// ---------------------------------------------------------------------------
extern "C" void kernel_launch(void* const* d_in, const int* in_sizes, int n_in,
                              void* d_out, int out_size)
{
    (void)in_sizes; (void)n_in; (void)out_size;

    const float* x  = (const float*)d_in[0];
    const float* w0 = (const float*)d_in[1];
    const float* b0 = (const float*)d_in[2];
    const float* w1 = (const float*)d_in[3];
    const float* b1 = (const float*)d_in[4];
    const float* w2 = (const float*)d_in[5];
    const float* b2 = (const float*)d_in[6];
    float* out = (float*)d_out;

    void *ph, *py1, *py2;
    cudaGetSymbolAddress(&ph,  g_h);
    cudaGetSymbolAddress(&py1, g_y1);
    cudaGetSymbolAddress(&py2, g_y2);

    // tileA + tileB + per-warp weight double buffers
    constexpr int SMEMC = (2 * TSZ) * 4 + 8 * 2 * 200 * 8;  // 164,864 B
    constexpr int SMEM3 = (64 * 8 * PW + 1600) * 4;         // 145,664 B

    cudaFuncSetAttribute(conv5x5_relu<32>,
                         cudaFuncAttributeMaxDynamicSharedMemorySize, SMEMC);
    cudaFuncSetAttribute(conv5x5_relu<64>,
                         cudaFuncAttributeMaxDynamicSharedMemorySize, SMEMC);
    cudaFuncSetAttribute(conv3k,
                         cudaFuncAttributeMaxDynamicSharedMemorySize, SMEM3);

    rotate_kernel<<<BB * CC, 128>>>(x, (float*)ph);
    zero_borders<<<BB * 64, 128>>>((float*)py1, (float*)py2);
    conv5x5_relu<32><<<BB * 16, 256, SMEMC>>>((const float*)ph, w0, b0, (float*)py1);
    conv5x5_relu<64><<<BB * 16, 256, SMEMC>>>((const float*)py1, w1, b1, (float*)py2);
    conv3k<<<BB * 16, 256, SMEM3>>>((const float*)py2, w2, b2, out);
}

// round 7
// speedup vs baseline: 1.6874x; 1.2264x over previous
#include <cuda_runtime.h>
#include <cstdint>
#include <cstddef>

// Problem constants (fixed by the reference)
#define BB 256
#define CC 32
#define HH 64
#define WW 64
#define PW 68           // padded width/height (2-px zero ring for 5x5 SAME)
#define PIMG (PW*PW)    // 4624

#define CHUNK 16        // input channels per tile pass
#define TROWS 8         // padded rows per tile (4 output rows + 4 halo)
#define TSZ   (CHUNK*TROWS*PW)   // floats per tile copy = 8704

// ---------------------------------------------------------------------------
// Device-global scratch (allocation-free rule: __device__ globals only).
// ---------------------------------------------------------------------------
__device__ float g_h [(size_t)BB * CC * PIMG];   // rotated input, padded
__device__ float g_y1[(size_t)BB * 64 * PIMG];   // conv1 output, padded
__device__ float g_y2[(size_t)BB * 64 * PIMG];   // conv2 output, padded

// ---------------------------------------------------------------------------
// Packed dual-fp32 helpers (Blackwell f32x2 path: 2x FFMA throughput)
// ---------------------------------------------------------------------------
__device__ __forceinline__ void fma2(unsigned long long& d,
                                     unsigned long long a,
                                     unsigned long long b) {
    asm("fma.rn.f32x2 %0, %1, %2, %0;" : "+l"(d) : "l"(a), "l"(b));
}

// ---------------------------------------------------------------------------
// Kernel 1: rotation (separable because source rows are replicated).
// ---------------------------------------------------------------------------
__global__ void rotate_kernel(const float* __restrict__ xin,
                              float* __restrict__ hout)
{
    const int bc = blockIdx.x;          // b*32 + c
    const int c  = bc & (CC - 1);

    __shared__ float row[WW];
    if (threadIdx.x < WW) row[threadIdx.x] = xin[(size_t)bc * WW + threadIdx.x];
    __syncthreads();

    const float ang = (-180.0f / 32.0f) * (float)c * 0.017453292519943295f;
    float si, co;
    sincosf(ang, &si, &co);

    float* dst = hout + (size_t)bc * PIMG;
    for (int p = threadIdx.x; p < PIMG; p += blockDim.x) {
        const int py = p / PW;
        const int px = p - py * PW;
        const int y = py - 2, x = px - 2;
        float val = 0.f;
        if ((unsigned)y < 64u && (unsigned)x < 64u) {
            const float xx = (float)x - 31.5f;
            const float yy = (float)y - 31.5f;
            const float xs = co * xx + si * yy + 31.5f;
            const float ys = co * yy - si * xx + 31.5f;
            const float x0f = floorf(xs);
            const float y0f = floorf(ys);
            const int x0  = (int)x0f;
            const int y0i = (int)y0f;
            const float wx1 = xs - x0f, wx0 = 1.f - wx1;
            const float wy1 = ys - y0f, wy0 = 1.f - wy1;
            float fy = 0.f;
            if ((unsigned)y0i       < 64u) fy += wy0;
            if ((unsigned)(y0i + 1) < 64u) fy += wy1;
            float fx = 0.f;
            if ((unsigned)x0       < 64u) fx += wx0 * row[x0];
            if ((unsigned)(x0 + 1) < 64u) fx += wx1 * row[x0 + 1];
            val = fy * fx;
        }
        dst[p] = val;
    }
}

// ---------------------------------------------------------------------------
// Re-zero the padding rings of the conv scratch buffers each launch.
// ---------------------------------------------------------------------------
__global__ void zero_borders(float* __restrict__ a, float* __restrict__ b)
{
    const int bc = blockIdx.x;          // b*64 + ch
    float* pa = a + (size_t)bc * PIMG;
    float* pb = b + (size_t)bc * PIMG;
    for (int p = threadIdx.x; p < 528; p += blockDim.x) {
        int off;
        if (p < 136)        off = p;                         // rows 0,1
        else if (p < 272)   off = 66 * PW + (p - 136);       // rows 66,67
        else {
            const int q = p - 272;
            const int r = 2 + (q >> 2);                      // rows 2..65
            const int cc4 = q & 3;
            const int col = (cc4 < 2) ? cc4 : 64 + cc4;      // cols 0,1,66,67
            off = r * PW + col;
        }
        pa[off] = 0.f;
        pb[off] = 0.f;
    }
}

// ---------------------------------------------------------------------------
// 5x5 SAME conv, CIN -> 64, ReLU. Block = (image, 4-row tile), 256 thr,
// __launch_bounds__(256,2) -> <=128 regs so 2 blocks/SM coreside.
//   warp w -> oc [8w,8w+8); lane l -> cols {2l,2l+1} in one f32x2 acc.
// smem: tileA (raw) + tileB (shifted by 1 float -> odd-kx pairs are aligned
//       LDS.64) + per-warp double-buffered dup-weights.
// Inner loop is kx-innermost: only 1 weight u64 + 4 row pairs live at once,
// keeping the register footprint under the 2-block budget.
// ---------------------------------------------------------------------------
template <int CIN>
__global__ void __launch_bounds__(256, 2)
conv5x5_relu(const float* __restrict__ in,    // [B][CIN][68][68]
             const float* __restrict__ w,     // [64][CIN][5][5]
             const float* __restrict__ bias,  // [64]
             float* __restrict__ out)         // [B][64][68][68]
{
    extern __shared__ float smem[];
    float*  tileA = smem;                      // TSZ floats
    float*  tileB = smem + TSZ;                // TSZ floats (shifted copy)
    float2* wsm   = (float2*)(smem + 2 * TSZ); // 8 warps x 2 bufs x 200 float2

    const int blk   = blockIdx.x;
    const int ytile = blk & 15;
    const int b     = blk >> 4;
    const int y0    = ytile * 4;

    const int warp   = threadIdx.x >> 5;
    const int lane   = threadIdx.x & 31;
    const int ocbase = warp * 8;

    // --- weight prefetch for channel 0 (warp's 8 oc x 25 = 200 floats) ---
    float wreg[7];
#pragma unroll
    for (int it = 0; it < 7; ++it) {
        const int idx = lane + it * 32;
        if (idx < 200) {
            const int jo = idx / 25, k = idx - jo * 25;
            wreg[it] = w[((size_t)(ocbase + jo) * CIN + 0) * 25 + k];
        }
    }

    unsigned long long acc[8][4];
#pragma unroll
    for (int j = 0; j < 8; ++j)
#pragma unroll
        for (int yr = 0; yr < 4; ++yr) acc[j][yr] = 0ull;

    constexpr int NCHUNK = CIN / CHUNK;
#pragma unroll 1
    for (int chunk = 0; chunk < NCHUNK; ++chunk) {
        // ---- load tile for channels [chunk*CHUNK, +CHUNK): raw + shifted ----
        __syncthreads();   // previous chunk fully consumed
        const float* src = in + ((size_t)b * CIN + chunk * CHUNK) * PIMG
                              + (size_t)y0 * PW;
#pragma unroll 1
        for (int i = threadIdx.x; i < TSZ; i += 256) {
            const int ch = i / (TROWS * PW);
            const int r  = i - ch * (TROWS * PW);
            const int x  = r % PW;
            const float v = src[(size_t)ch * PIMG + r];
            tileA[i] = v;
            if (x > 0) tileB[i - 1] = v;
        }
        __syncthreads();

#pragma unroll 1
        for (int cl = 0; cl < CHUNK; ++cl) {
            const int c = chunk * CHUNK + cl;

            // ---- stage prefetched weights (channel c) to smem, dup'd ----
            float2* wb = wsm + (size_t)(warp * 2 + (c & 1)) * 200;
#pragma unroll
            for (int it = 0; it < 7; ++it) {
                const int idx = lane + it * 32;
                if (idx < 200) wb[idx] = make_float2(wreg[it], wreg[it]);
            }
            __syncwarp();

            // ---- prefetch channel c+1 weights into registers ----
            if (c + 1 < CIN) {
#pragma unroll
                for (int it = 0; it < 7; ++it) {
                    const int idx = lane + it * 32;
                    if (idx < 200) {
                        const int jo = idx / 25, k = idx - jo * 25;
                        wreg[it] = w[((size_t)(ocbase + jo) * CIN + (c + 1)) * 25 + k];
                    }
                }
            }

            // ---- compute: kx-innermost, all operands aligned LDS.64 ----
            const float* ta = tileA + cl * (TROWS * PW) + 2 * lane;
            const float* tb = tileB + cl * (TROWS * PW) + 2 * lane;
            const unsigned long long* wu = (const unsigned long long*)wb;
#pragma unroll
            for (int ky = 0; ky < 5; ++ky) {
#pragma unroll
                for (int kx = 0; kx < 5; ++kx) {
                    // column pair for this kx: even kx from tileA, odd from tileB
                    const float* tsrc = (kx & 1) ? tb : ta;
                    const int xoff = (kx >> 1) * 2;
                    unsigned long long p[4];
#pragma unroll
                    for (int yr = 0; yr < 4; ++yr)
                        p[yr] = *(const unsigned long long*)
                                    (tsrc + (ky + yr) * PW + xoff);
#pragma unroll
                    for (int j = 0; j < 8; ++j) {
                        const unsigned long long wv = wu[j * 25 + ky * 5 + kx];
#pragma unroll
                        for (int yr = 0; yr < 4; ++yr)
                            fma2(acc[j][yr], wv, p[yr]);
                    }
                }
            }
        }
    }

    // ---- epilogue: bias + ReLU, write padded interior ----
    const size_t ob = (size_t)b * 64;
#pragma unroll
    for (int j = 0; j < 8; ++j) {
        const int oc = ocbase + j;
        const float bv = bias[oc];
#pragma unroll
        for (int yr = 0; yr < 4; ++yr) {
            const float lo = __uint_as_float((unsigned)(acc[j][yr] & 0xffffffffull));
            const float hi = __uint_as_float((unsigned)(acc[j][yr] >> 32));
            float2 o;
            o.x = fmaxf(lo + bv, 0.f);
            o.y = fmaxf(hi + bv, 0.f);
            *(float2*)(out + (ob + oc) * PIMG
                           + (size_t)(y0 + 2 + yr) * PW + 2 + 2 * lane) = o;
        }
    }
}

// ---------------------------------------------------------------------------
// Final 5x5 conv, 64 -> 1, writes d_out (B,64,64). Channel-chunked smem so
// multiple blocks coreside (was 1 block/SM at 146 KB).
// ---------------------------------------------------------------------------
__global__ void __launch_bounds__(256, 2)
conv3k(const float* __restrict__ in,   // [B][64][68][68]
       const float* __restrict__ w2,   // [1][64][5][5]
       const float* __restrict__ b2,   // [1]
       float* __restrict__ out)        // [B][64][64]
{
    extern __shared__ float smem[];
    float* tile = smem;                     // CHUNK*8*68
    float* ws   = smem + CHUNK * 8 * PW;    // 1600

    const int blk   = blockIdx.x;
    const int ytile = blk & 15;
    const int b     = blk >> 4;
    const int y0    = ytile * 4;

    for (int i = threadIdx.x; i < 1600; i += 256) ws[i] = w2[i];

    const int yr = threadIdx.x >> 6;    // 0..3
    const int x  = threadIdx.x & 63;    // 0..63
    float acc = b2[0];

#pragma unroll 1
    for (int chunk = 0; chunk < 64 / CHUNK; ++chunk) {
        __syncthreads();
        const float* src = in + ((size_t)b * 64 + chunk * CHUNK) * PIMG
                              + (size_t)y0 * PW;
        for (int i = threadIdx.x; i < CHUNK * 8 * PW; i += 256) {
            const int ch = i / (8 * PW);
            const int r  = i - ch * (8 * PW);
            tile[i] = src[(size_t)ch * PIMG + r];
        }
        __syncthreads();

#pragma unroll 1
        for (int cl = 0; cl < CHUNK; ++cl) {
            const float* t  = tile + cl * (8 * PW) + yr * PW + x;
            const float* wc = ws + (chunk * CHUNK + cl) * 25;
#pragma unroll
            for (int ky = 0; ky < 5; ++ky)
#pragma unroll
                for (int kx = 0; kx < 5; ++kx)
                    acc += wc[ky * 5 + kx] * t[ky * PW + kx];
        }
    }
    out[(size_t)b * 4096 + (size_t)(y0 + yr) * 64 + x] = acc;
}

// ---------------------------------------------------------------------------
// kernel_launch (graph-capturable: kernel launches + non-stream queries only)
// Input order per metadata: x, w0, b0, w1, b1, w2, b2 (all fp32).
// ---------------------------------------------------------------------------
extern "C" void kernel_launch(void* const* d_in, const int* in_sizes, int n_in,
                              void* d_out, int out_size)
{
    (void)in_sizes; (void)n_in; (void)out_size;

    const float* x  = (const float*)d_in[0];
    const float* w0 = (const float*)d_in[1];
    const float* b0 = (const float*)d_in[2];
    const float* w1 = (const float*)d_in[3];
    const float* b1 = (const float*)d_in[4];
    const float* w2 = (const float*)d_in[5];
    const float* b2 = (const float*)d_in[6];
    float* out = (float*)d_out;

    void *ph, *py1, *py2;
    cudaGetSymbolAddress(&ph,  g_h);
    cudaGetSymbolAddress(&py1, g_y1);
    cudaGetSymbolAddress(&py2, g_y2);

    // tileA + tileB + per-warp weight double buffers
    constexpr int SMEMC = (2 * TSZ) * 4 + 8 * 2 * 200 * 8;   // 95,232 B
    constexpr int SMEM3 = (CHUNK * 8 * PW + 1600) * 4;       // 41,216 B

    cudaFuncSetAttribute(conv5x5_relu<32>,
                         cudaFuncAttributeMaxDynamicSharedMemorySize, SMEMC);
    cudaFuncSetAttribute(conv5x5_relu<64>,
                         cudaFuncAttributeMaxDynamicSharedMemorySize, SMEMC);
    cudaFuncSetAttribute(conv3k,
                         cudaFuncAttributeMaxDynamicSharedMemorySize, SMEM3);

    rotate_kernel<<<BB * CC, 128>>>(x, (float*)ph);
    zero_borders<<<BB * 64, 128>>>((float*)py1, (float*)py2);
    conv5x5_relu<32><<<BB * 16, 256, SMEMC>>>((const float*)ph, w0, b0, (float*)py1);
    conv5x5_relu<64><<<BB * 16, 256, SMEMC>>>((const float*)py1, w1, b1, (float*)py2);
    conv3k<<<BB * 16, 256, SMEM3>>>((const float*)py2, w2, b2, out);
}